// round 11
// baseline (speedup 1.0000x reference)
#include <cuda_runtime.h>
#include <cuda_fp16.h>
#include <mma.h>
#include <cstdint>

using namespace nvcuda;

// ---------------------------------------------------------------------------
// Problem constants
// ---------------------------------------------------------------------------
#define B_    32
#define C_    256
#define H_    56
#define W_    56
#define HW_   3136            // 56*56
#define O_    512
#define KK_   2304            // C*9
#define NPIX  100352          // B*HW

// GEMM tiling
#define BM 128
#define BN 128
#define BK 64
#define NCHUNK 36             // 2304 / 64
#define NTHREADS 512

// SMEM stage layout: A 128 rows x 144B, B 128 rows x 144B (row = 64 halfs + 8 pad)
#define ROW_B     144
#define A_BYTES   (128 * ROW_B)       // 18432
#define B_BYTES   (128 * ROW_B)       // 18432
#define STAGE_B   (A_BYTES + B_BYTES) // 36864
#define NSTAGES   3
#define SM_META   (NSTAGES * STAGE_B) // 110592
#define SMEM_TOTAL (SM_META + 1280)   // 111872  (2 CTAs/SM: 2x <= 227KB)

// ---------------------------------------------------------------------------
// Device scratch (no runtime allocation)
// ---------------------------------------------------------------------------
__device__ __half d_Wh[O_ * KK_];     // weights fp16, [o][k'], k' = tap*256 + c
#define XPAD 16384
__device__ __half d_xt_buf[XPAD + (size_t)B_ * HW_ * C_ + XPAD]; // x^T: [b][hw][c]
__device__ int    d_mask_kind;        // 0=uint8, 1=int32, 2=float32

// ---------------------------------------------------------------------------
// Helpers
// ---------------------------------------------------------------------------
__device__ __forceinline__ uint32_t smem_to_u32(const void* p) {
    uint32_t a;
    asm("{ .reg .u64 t; cvta.to.shared.u64 t, %1; cvt.u32.u64 %0, t; }" : "=r"(a) : "l"(p));
    return a;
}

__device__ __forceinline__ void cp_async16(uint32_t dst, const void* src, int src_size) {
    asm volatile("cp.async.cg.shared.global [%0], [%1], 16, %2;"
                 :: "r"(dst), "l"(src), "r"(src_size) : "memory");
}
__device__ __forceinline__ void cp_commit() {
    asm volatile("cp.async.commit_group;" ::: "memory");
}
__device__ __forceinline__ void cp_wait1() {
    asm volatile("cp.async.wait_group 1;" ::: "memory");
}

// ---------------------------------------------------------------------------
// Mask dtype sniffing
// ---------------------------------------------------------------------------
__global__ void detect_mask_kernel(const unsigned int* __restrict__ pos) {
    __shared__ int any_big;
    __shared__ int any_f32;
    if (threadIdx.x == 0) { any_big = 0; any_f32 = 0; }
    __syncthreads();
    for (int i = threadIdx.x; i < 4096; i += 256) {
        unsigned int v = pos[i];
        if (v == 0x3F800000u) any_f32 = 1;
        else if (v > 1u)      any_big = 1;
    }
    __syncthreads();
    if (threadIdx.x == 0) d_mask_kind = any_f32 ? 2 : (any_big ? 0 : 1);
}

// ---------------------------------------------------------------------------
// Weights: masks (K,O) -> fp16 [o][k'] with k' = tap*256 + c   (k = c*9 + tap)
// ---------------------------------------------------------------------------
__global__ void prep_w_kernel(const void* __restrict__ posv,
                              const void* __restrict__ negv) {
    int i = blockIdx.x * 256 + threadIdx.x;   // over K*O
    if (i >= KK_ * O_) return;
    int k = i / O_;
    int o = i - k * O_;
    float p, n;
    int kind = d_mask_kind;
    if (kind == 1)      { p = (float)((const int*)posv)[i];   n = (float)((const int*)negv)[i]; }
    else if (kind == 2) { p = ((const float*)posv)[i];        n = ((const float*)negv)[i]; }
    else                { p = (float)((const unsigned char*)posv)[i];
                          n = (float)((const unsigned char*)negv)[i]; }
    int c = k / 9;
    int t = k - c * 9;
    d_Wh[o * KK_ + t * 256 + c] = __float2half(p - n);
}

// ---------------------------------------------------------------------------
// x (b,c,hw) fp32 -> x^T (b,hw,c) fp16, tiled SMEM transpose
// ---------------------------------------------------------------------------
__global__ void prep_xt_kernel(const float* __restrict__ x) {
    __shared__ __half tile[32][33];
    int hw0 = blockIdx.x * 32;
    int c0  = blockIdx.y * 32;
    int b   = blockIdx.z;
    int tx = threadIdx.x, ty = threadIdx.y;
    const float* xp = x + (size_t)b * C_ * HW_;
#pragma unroll
    for (int r = 0; r < 32; r += 8)
        tile[ty + r][tx] = __float2half(xp[(size_t)(c0 + ty + r) * HW_ + hw0 + tx]);
    __syncthreads();
    __half* xt = d_xt_buf + XPAD + (size_t)b * HW_ * C_;
#pragma unroll
    for (int r = 0; r < 32; r += 8)
        xt[(size_t)(hw0 + ty + r) * C_ + c0 + tx] = tile[tx][ty + r];
}

// ---------------------------------------------------------------------------
// Implicit-GEMM conv, wmma + 3-stage cp.async pipeline (BK=64), 2 CTAs/SM.
// CTA: BM=128 o-channels x BN=128 pixels. 16 warps, warp grid 4(M) x 4(N),
// warp tile 32x32 -> acc[2][2] wmma 16x16x16 fragments (f16 in, f32 acc).
// 32 warps/SM (8 per SMSP) for latency hiding; regs capped at 64/thread.
// K chunks: 36 x 64 (one tap x 64 contiguous channels in x^T layout).
// ---------------------------------------------------------------------------
__global__ __launch_bounds__(NTHREADS, 2)
void conv_gemm_kernel(float* __restrict__ out) {
    extern __shared__ __align__(1024) char smem[];
    const uint32_t smem_base = smem_to_u32(smem);
    const int tid = threadIdx.x;

    int* sXoff = (int*)(smem + SM_META);          // (b*HW + hw) * C
    int* sHW   = (int*)(smem + SM_META + 512);    // h<<16 | w
    int* sNB   = (int*)(smem + SM_META + 1024);   // per 4-pixel group: b*O*HW + hw

    const int n0 = blockIdx.x * BN;    // pixel tile
    const int m0 = blockIdx.y * BM;    // output-channel tile

    if (tid < BN) {
        int n  = n0 + tid;
        int b  = n / HW_;
        int hw = n - b * HW_;
        int h  = hw / W_;
        int w  = hw - h * W_;
        sXoff[tid] = (b * HW_ + hw) * C_;
        sHW[tid]   = (h << 16) | w;
    }
    if (tid < BN / 4) {
        int n  = n0 + 4 * tid;
        int b  = n / HW_;
        int hw = n - b * HW_;
        sNB[tid] = b * (O_ * HW_) + hw;
    }
    __syncthreads();

    // ---- hoisted loader state ----
    // task idx = tid + 512*r: seg = tid&7 (constant), m/j = (tid>>3) + 64r, r<2
    const int sg      = tid & 7;
    const int mj_base = tid >> 3;    // 0..63

    const __half*  aSrcBase = d_Wh + (size_t)(m0 + mj_base) * KK_ + sg * 8;
    const uint32_t aOffBase = smem_base + mj_base * ROW_B + sg * 16;

    const __half* bSrc[2];
    uint32_t      bOff[2];
    uint32_t      vmask[2];   // bit t set => tap t in-bounds for this pixel
#pragma unroll
    for (int r = 0; r < 2; ++r) {
        int j   = mj_base + 64 * r;
        int hwp = sHW[j];
        int h = hwp >> 16, w = hwp & 0xFFFF;
        uint32_t msk = 0;
#pragma unroll
        for (int t = 0; t < 9; ++t) {
            int dh = t / 3 - 1;
            int dw = t - (t / 3) * 3 - 1;
            if ((unsigned)(h + dh) < (unsigned)H_ && (unsigned)(w + dw) < (unsigned)W_)
                msk |= 1u << t;
        }
        vmask[r] = msk;
        bSrc[r]  = d_xt_buf + XPAD + sXoff[j] + sg * 8;
        bOff[r]  = smem_base + A_BYTES + j * ROW_B + sg * 16;
    }

    // ---- stage loader: chunk i -> stage i % NSTAGES ----
    auto issue_loads = [&](int i) {
        const int s    = i % NSTAGES;
        const int t    = i >> 2;                  // tap 0..8 (4 chunks per tap)
        const int dh   = t / 3 - 1;
        const int dw   = t - (t / 3) * 3 - 1;
        const int koff = i * BK;                  // == t*256 + (i&3)*64
        const int boff = (dh * W_ + dw) * C_ + (i & 3) * BK;
        const uint32_t sb = (uint32_t)(s * STAGE_B);
#pragma unroll
        for (int r = 0; r < 2; ++r)
            cp_async16(aOffBase + sb + r * (64 * ROW_B),
                       aSrcBase + koff + (size_t)r * (64 * KK_), 16);
#pragma unroll
        for (int r = 0; r < 2; ++r)
            cp_async16(bOff[r] + sb, bSrc[r] + boff,
                       ((vmask[r] >> t) & 1u) ? 16 : 0);
    };

    const int wid = tid >> 5;
    const int wm  = wid >> 2;   // 0..3 (M)
    const int wn  = wid & 3;    // 0..3 (N)

    wmma::fragment<wmma::accumulator, 16, 16, 16, float> acc[2][2];
#pragma unroll
    for (int im = 0; im < 2; ++im)
#pragma unroll
        for (int in = 0; in < 2; ++in)
            wmma::fill_fragment(acc[im][in], 0.0f);

    // ---- prologue: 2 stages in flight ----
#pragma unroll
    for (int i = 0; i < NSTAGES - 1; ++i) { issue_loads(i); cp_commit(); }

    // ---- main loop ----
    for (int i = 0; i < NCHUNK; ++i) {
        cp_wait1();
        __syncthreads();

        const int s = i % NSTAGES;
        const __half* as = (const __half*)(smem + s * STAGE_B);
        const __half* bs = (const __half*)(smem + s * STAGE_B + A_BYTES);
#pragma unroll
        for (int kk = 0; kk < BK; kk += 16) {
            wmma::fragment<wmma::matrix_a, 16, 16, 16, __half, wmma::row_major> af[2];
            wmma::fragment<wmma::matrix_b, 16, 16, 16, __half, wmma::col_major> bf[2];
#pragma unroll
            for (int im = 0; im < 2; ++im)
                wmma::load_matrix_sync(af[im], as + (wm * 32 + im * 16) * 72 + kk, 72);
#pragma unroll
            for (int in = 0; in < 2; ++in)
                wmma::load_matrix_sync(bf[in], bs + (wn * 32 + in * 16) * 72 + kk, 72);
#pragma unroll
            for (int im = 0; im < 2; ++im)
#pragma unroll
                for (int in = 0; in < 2; ++in)
                    wmma::mma_sync(acc[im][in], af[im], bf[in], acc[im][in]);
        }

        if (i + NSTAGES - 1 < NCHUNK) issue_loads(i + NSTAGES - 1);
        cp_commit();   // unconditional: keeps wait_group accounting exact
    }
    __syncthreads();

    // ---- epilogue: 4 passes of 32 M-rows through SMEM, float4 scatter ----
    float* Cs = (float*)smem;   // [32][132]
#pragma unroll 1
    for (int pass = 0; pass < 4; ++pass) {
        if (wm == pass) {
#pragma unroll
            for (int im = 0; im < 2; ++im)
#pragma unroll
                for (int in = 0; in < 2; ++in)
                    wmma::store_matrix_sync(Cs + (im * 16) * 132 + wn * 32 + in * 16,
                                            acc[im][in], 132, wmma::mem_row_major);
        }
        __syncthreads();
#pragma unroll
        for (int r = 0; r < 2; ++r) {
            int e = tid + NTHREADS * r;       // 1024 float4 tasks
            int m = e >> 5;                   // 0..31 row
            int q = e & 31;                   // 4-pixel group
            float4 v = *(const float4*)(Cs + m * 132 + q * 4);
            *(float4*)(out + sNB[q] + (size_t)(m0 + pass * 32 + m) * HW_) = v;
        }
        __syncthreads();
    }
}

// ---------------------------------------------------------------------------
// Launch
// ---------------------------------------------------------------------------
extern "C" void kernel_launch(void* const* d_in, const int* in_sizes, int n_in,
                              void* d_out, int out_size) {
    const float* x   = (const float*)d_in[0];
    const void*  pos = d_in[1];
    const void*  neg = d_in[2];
    float* out = (float*)d_out;

    static bool attr_set = false;
    if (!attr_set) {
        cudaFuncSetAttribute(conv_gemm_kernel,
                             cudaFuncAttributeMaxDynamicSharedMemorySize, SMEM_TOTAL);
        attr_set = true;
    }

    // 0) sniff mask representation
    detect_mask_kernel<<<1, 256>>>((const unsigned int*)pos);
    // 1) weights -> fp16 [o][k'] (tap-major K permutation)
    prep_w_kernel<<<(KK_ * O_ + 255) / 256, 256>>>(pos, neg);
    // 2) x -> fp16 transposed [b][hw][c]
    dim3 tgrid(HW_ / 32, C_ / 32, B_);
    prep_xt_kernel<<<tgrid, dim3(32, 8)>>>(x);
    // 3) wmma implicit GEMM: grid = (784 pixel tiles, 4 m tiles), 2 CTAs/SM
    dim3 grid(NPIX / BN, O_ / BM);
    conv_gemm_kernel<<<grid, NTHREADS, SMEM_TOTAL>>>(out);
}

// round 13
// speedup vs baseline: 1.7419x; 1.7419x over previous
#include <cuda_runtime.h>
#include <cuda_fp16.h>
#include <mma.h>
#include <cstdint>

using namespace nvcuda;

// ---------------------------------------------------------------------------
// Problem constants
// ---------------------------------------------------------------------------
#define B_    32
#define C_    256
#define H_    56
#define W_    56
#define HW_   3136            // 56*56
#define O_    512
#define KK_   2304            // C*9
#define NPIX  100352          // B*HW

// GEMM tiling
#define BM 128
#define BN 128
#define BK 64
#define NCHUNK 36             // 2304 / 64
#define NTHREADS 256

// SMEM stage layout: A 128 rows x 144B, B 128 rows x 144B (row = 64 halfs + 8 pad)
#define ROW_B     144
#define A_BYTES   (128 * ROW_B)       // 18432
#define B_BYTES   (128 * ROW_B)       // 18432
#define STAGE_B   (A_BYTES + B_BYTES) // 36864
#define NSTAGES   3
#define SM_META   (NSTAGES * STAGE_B) // 110592
#define SMEM_TOTAL (SM_META + 1280)   // 111872  (2 CTAs/SM: 2x <= 227KB)

// ---------------------------------------------------------------------------
// Device scratch (no runtime allocation)
// ---------------------------------------------------------------------------
__device__ __half d_Wh[O_ * KK_];     // weights fp16, [o][k'], k' = tap*256 + c
#define XPAD 16384
__device__ __half d_xt_buf[XPAD + (size_t)B_ * HW_ * C_ + XPAD]; // x^T: [b][hw][c]
__device__ int    d_mask_kind;        // 0=uint8, 1=int32, 2=float32

// ---------------------------------------------------------------------------
// Helpers
// ---------------------------------------------------------------------------
__device__ __forceinline__ uint32_t smem_to_u32(const void* p) {
    uint32_t a;
    asm("{ .reg .u64 t; cvta.to.shared.u64 t, %1; cvt.u32.u64 %0, t; }" : "=r"(a) : "l"(p));
    return a;
}

__device__ __forceinline__ void cp_async16(uint32_t dst, const void* src, int src_size) {
    asm volatile("cp.async.cg.shared.global [%0], [%1], 16, %2;"
                 :: "r"(dst), "l"(src), "r"(src_size) : "memory");
}
__device__ __forceinline__ void cp_commit() {
    asm volatile("cp.async.commit_group;" ::: "memory");
}
__device__ __forceinline__ void cp_wait1() {
    asm volatile("cp.async.wait_group 1;" ::: "memory");
}

// ---------------------------------------------------------------------------
// Mask dtype sniffing
// ---------------------------------------------------------------------------
__global__ void detect_mask_kernel(const unsigned int* __restrict__ pos) {
    __shared__ int any_big;
    __shared__ int any_f32;
    if (threadIdx.x == 0) { any_big = 0; any_f32 = 0; }
    __syncthreads();
    for (int i = threadIdx.x; i < 4096; i += 256) {
        unsigned int v = pos[i];
        if (v == 0x3F800000u) any_f32 = 1;
        else if (v > 1u)      any_big = 1;
    }
    __syncthreads();
    if (threadIdx.x == 0) d_mask_kind = any_f32 ? 2 : (any_big ? 0 : 1);
}

// ---------------------------------------------------------------------------
// Weights: masks (K,O) -> fp16 [o][k'] with k' = tap*256 + c   (k = c*9 + tap)
// ---------------------------------------------------------------------------
__global__ void prep_w_kernel(const void* __restrict__ posv,
                              const void* __restrict__ negv) {
    int i = blockIdx.x * 256 + threadIdx.x;   // over K*O
    if (i >= KK_ * O_) return;
    int k = i / O_;
    int o = i - k * O_;
    float p, n;
    int kind = d_mask_kind;
    if (kind == 1)      { p = (float)((const int*)posv)[i];   n = (float)((const int*)negv)[i]; }
    else if (kind == 2) { p = ((const float*)posv)[i];        n = ((const float*)negv)[i]; }
    else                { p = (float)((const unsigned char*)posv)[i];
                          n = (float)((const unsigned char*)negv)[i]; }
    int c = k / 9;
    int t = k - c * 9;
    d_Wh[o * KK_ + t * 256 + c] = __float2half(p - n);
}

// ---------------------------------------------------------------------------
// x (b,c,hw) fp32 -> x^T (b,hw,c) fp16, tiled SMEM transpose.
// Tile: 64 channels x 32 pixels. Loads: float per lane (128B/warp), 8 rows/thread.
// Stores: half2 (uint) per lane (128B/warp), 4 hw-rows/thread (32 rows / 8 ty).
// grid (HW/32, C/64, B), block (32, 8)
// ---------------------------------------------------------------------------
__global__ void prep_xt_kernel(const float* __restrict__ x) {
    __shared__ __half tile[64][33];    // [c][hw], padded
    int hw0 = blockIdx.x * 32;
    int c0  = blockIdx.y * 64;
    int b   = blockIdx.z;
    int tx = threadIdx.x, ty = threadIdx.y;
    const float* xp = x + (size_t)b * C_ * HW_;
    // load 64 c-rows x 32 hw: each thread 8 rows
#pragma unroll
    for (int r = 0; r < 8; ++r)
        tile[ty + 8 * r][tx] = __float2half(xp[(size_t)(c0 + ty + 8 * r) * HW_ + hw0 + tx]);
    __syncthreads();
    // store 32 hw-rows x 64 c as 32 uints per row: each thread 4 rows, 1 uint/row
    unsigned int* xt2 = reinterpret_cast<unsigned int*>(
        d_xt_buf + XPAD + (size_t)b * HW_ * C_);
#pragma unroll
    for (int r = 0; r < 4; ++r) {              // 32 hw rows / 8 ty lanes
        int hwrow = ty + 8 * r;                // 0..31
        __half lo = tile[2 * tx][hwrow];
        __half hi = tile[2 * tx + 1][hwrow];
        __half2 v = __halves2half2(lo, hi);
        xt2[(size_t)(hw0 + hwrow) * (C_ / 2) + c0 / 2 + tx] =
            *reinterpret_cast<unsigned int*>(&v);
    }
}

// ---------------------------------------------------------------------------
// Implicit-GEMM conv, wmma + 3-stage cp.async pipeline (BK=64), 2 CTAs/SM.
// CTA: BM=128 o-channels x BN=128 pixels. 8 warps, warp grid 4(M) x 2(N),
// warp tile 32x64 -> acc[2][4] wmma 16x16x16 fragments (f16 in, f32 acc).
// K chunks: 36 x 64 (one tap x 64 contiguous channels in x^T layout).
// Loader state hoisted to registers (base pointers + 9-bit tap validity
// masks); load issue AFTER the MMA block (known-good R10 order).
// ---------------------------------------------------------------------------
__global__ __launch_bounds__(NTHREADS, 2)
void conv_gemm_kernel(float* __restrict__ out) {
    extern __shared__ __align__(1024) char smem[];
    const uint32_t smem_base = smem_to_u32(smem);
    const int tid = threadIdx.x;

    int* sXoff = (int*)(smem + SM_META);          // (b*HW + hw) * C
    int* sHW   = (int*)(smem + SM_META + 512);    // h<<16 | w
    int* sNB   = (int*)(smem + SM_META + 1024);   // per 4-pixel group: b*O*HW + hw

    const int n0 = blockIdx.x * BN;    // pixel tile
    const int m0 = blockIdx.y * BM;    // output-channel tile

    if (tid < BN) {
        int n  = n0 + tid;
        int b  = n / HW_;
        int hw = n - b * HW_;
        int h  = hw / W_;
        int w  = hw - h * W_;
        sXoff[tid] = (b * HW_ + hw) * C_;
        sHW[tid]   = (h << 16) | w;
    }
    if (tid < BN / 4) {
        int n  = n0 + 4 * tid;
        int b  = n / HW_;
        int hw = n - b * HW_;
        sNB[tid] = b * (O_ * HW_) + hw;
    }
    __syncthreads();

    // ---- hoisted loader state ----
    // task idx = tid + 256*r: seg = tid&7 (constant), m/j = (tid>>3)+32r
    const int sg      = tid & 7;
    const int mj_base = tid >> 3;

    const __half*  aSrcBase = d_Wh + (size_t)(m0 + mj_base) * KK_ + sg * 8;
    const uint32_t aOffBase = smem_base + mj_base * ROW_B + sg * 16;

    const __half* bSrc[4];
    uint32_t      bOff[4];
    uint32_t      vmask[4];   // bit t set => tap t in-bounds for this pixel
#pragma unroll
    for (int r = 0; r < 4; ++r) {
        int j   = mj_base + 32 * r;
        int hwp = sHW[j];
        int h = hwp >> 16, w = hwp & 0xFFFF;
        uint32_t msk = 0;
#pragma unroll
        for (int t = 0; t < 9; ++t) {
            int dh = t / 3 - 1;
            int dw = t - (t / 3) * 3 - 1;
            if ((unsigned)(h + dh) < (unsigned)H_ && (unsigned)(w + dw) < (unsigned)W_)
                msk |= 1u << t;
        }
        vmask[r] = msk;
        bSrc[r]  = d_xt_buf + XPAD + sXoff[j] + sg * 8;
        bOff[r]  = smem_base + A_BYTES + j * ROW_B + sg * 16;
    }

    // ---- stage loader: chunk i -> stage i % NSTAGES ----
    auto issue_loads = [&](int i) {
        const int s    = i % NSTAGES;
        const int t    = i >> 2;                  // tap 0..8 (4 chunks per tap)
        const int dh   = t / 3 - 1;
        const int dw   = t - (t / 3) * 3 - 1;
        const int koff = i * BK;                  // == t*256 + (i&3)*64
        const int boff = (dh * W_ + dw) * C_ + (i & 3) * BK;
        const uint32_t sb = (uint32_t)(s * STAGE_B);
#pragma unroll
        for (int r = 0; r < 4; ++r)
            cp_async16(aOffBase + sb + r * (32 * ROW_B),
                       aSrcBase + koff + (size_t)r * (32 * KK_), 16);
#pragma unroll
        for (int r = 0; r < 4; ++r)
            cp_async16(bOff[r] + sb, bSrc[r] + boff,
                       ((vmask[r] >> t) & 1u) ? 16 : 0);
    };

    const int wid = tid >> 5;
    const int wm  = wid >> 1;   // 0..3 (M)
    const int wn  = wid & 1;    // 0..1 (N)

    wmma::fragment<wmma::accumulator, 16, 16, 16, float> acc[2][4];
#pragma unroll
    for (int im = 0; im < 2; ++im)
#pragma unroll
        for (int in = 0; in < 4; ++in)
            wmma::fill_fragment(acc[im][in], 0.0f);

    // ---- prologue: 2 stages in flight ----
#pragma unroll
    for (int i = 0; i < NSTAGES - 1; ++i) { issue_loads(i); cp_commit(); }

    // ---- main loop ----
    for (int i = 0; i < NCHUNK; ++i) {
        cp_wait1();
        __syncthreads();

        const int s = i % NSTAGES;
        const __half* as = (const __half*)(smem + s * STAGE_B);
        const __half* bs = (const __half*)(smem + s * STAGE_B + A_BYTES);
#pragma unroll
        for (int kk = 0; kk < BK; kk += 16) {
            wmma::fragment<wmma::matrix_a, 16, 16, 16, __half, wmma::row_major> af[2];
            wmma::fragment<wmma::matrix_b, 16, 16, 16, __half, wmma::col_major> bf[4];
#pragma unroll
            for (int im = 0; im < 2; ++im)
                wmma::load_matrix_sync(af[im], as + (wm * 32 + im * 16) * 72 + kk, 72);
#pragma unroll
            for (int in = 0; in < 4; ++in)
                wmma::load_matrix_sync(bf[in], bs + (wn * 64 + in * 16) * 72 + kk, 72);
#pragma unroll
            for (int im = 0; im < 2; ++im)
#pragma unroll
                for (int in = 0; in < 4; ++in)
                    wmma::mma_sync(acc[im][in], af[im], bf[in], acc[im][in]);
        }

        if (i + NSTAGES - 1 < NCHUNK) issue_loads(i + NSTAGES - 1);
        cp_commit();   // unconditional: keeps wait_group accounting exact
    }
    __syncthreads();

    // ---- epilogue: 4 passes of 32 M-rows through SMEM, float4 scatter ----
    float* Cs = (float*)smem;   // [32][132]
#pragma unroll 1
    for (int pass = 0; pass < 4; ++pass) {
        if (wm == pass) {
#pragma unroll
            for (int im = 0; im < 2; ++im)
#pragma unroll
                for (int in = 0; in < 4; ++in)
                    wmma::store_matrix_sync(Cs + (im * 16) * 132 + wn * 64 + in * 16,
                                            acc[im][in], 132, wmma::mem_row_major);
        }
        __syncthreads();
#pragma unroll
        for (int r = 0; r < 4; ++r) {
            int e = tid + NTHREADS * r;       // 1024 float4 tasks
            int m = e >> 5;                   // 0..31 row
            int q = e & 31;                   // 4-pixel group
            float4 v = *(const float4*)(Cs + m * 132 + q * 4);
            *(float4*)(out + sNB[q] + (size_t)(m0 + pass * 32 + m) * HW_) = v;
        }
        __syncthreads();
    }
}

// ---------------------------------------------------------------------------
// Launch
// ---------------------------------------------------------------------------
extern "C" void kernel_launch(void* const* d_in, const int* in_sizes, int n_in,
                              void* d_out, int out_size) {
    const float* x   = (const float*)d_in[0];
    const void*  pos = d_in[1];
    const void*  neg = d_in[2];
    float* out = (float*)d_out;

    static bool attr_set = false;
    if (!attr_set) {
        cudaFuncSetAttribute(conv_gemm_kernel,
                             cudaFuncAttributeMaxDynamicSharedMemorySize, SMEM_TOTAL);
        attr_set = true;
    }

    // 0) sniff mask representation
    detect_mask_kernel<<<1, 256>>>((const unsigned int*)pos);
    // 1) weights -> fp16 [o][k'] (tap-major K permutation)
    prep_w_kernel<<<(KK_ * O_ + 255) / 256, 256>>>(pos, neg);
    // 2) x -> fp16 transposed [b][hw][c], vectorized stores
    dim3 tgrid(HW_ / 32, C_ / 64, B_);
    prep_xt_kernel<<<tgrid, dim3(32, 8)>>>(x);
    // 3) wmma implicit GEMM: grid = (784 pixel tiles, 4 m tiles), 2 CTAs/SM
    dim3 grid(NPIX / BN, O_ / BM);
    conv_gemm_kernel<<<grid, NTHREADS, SMEM_TOTAL>>>(out);
}

// round 14
// speedup vs baseline: 1.7420x; 1.0001x over previous
#include <cuda_runtime.h>
#include <cuda_fp16.h>
#include <mma.h>
#include <cstdint>

using namespace nvcuda;

// ---------------------------------------------------------------------------
// Problem constants
// ---------------------------------------------------------------------------
#define B_    32
#define C_    256
#define H_    56
#define W_    56
#define HW_   3136            // 56*56
#define O_    512
#define KK_   2304            // C*9
#define NPIX  100352          // B*HW

// GEMM tiling
#define BM 128
#define BN 128
#define BK 64
#define NCHUNK 36             // 2304 / 64
#define NTHREADS 256

// SMEM stage layout: A 128 rows x 144B, B 128 rows x 144B (row = 64 halfs + 8 pad)
#define ROW_B     144
#define A_BYTES   (128 * ROW_B)       // 18432
#define B_BYTES   (128 * ROW_B)       // 18432
#define STAGE_B   (A_BYTES + B_BYTES) // 36864
#define NSTAGES   3
#define SM_META   (NSTAGES * STAGE_B) // 110592
#define SMEM_TOTAL (SM_META + 1280)   // (2 CTAs/SM: 2x <= 227KB)

// ---------------------------------------------------------------------------
// Device scratch (no runtime allocation)
// ---------------------------------------------------------------------------
__device__ __half d_Wh[O_ * KK_];     // weights fp16, [o][k'], k' = tap*256 + c
#define XPAD 16384
__device__ __half d_xt_buf[XPAD + (size_t)B_ * HW_ * C_ + XPAD]; // x^T: [b][hw][c]
__device__ int    d_mask_kind;        // 0=uint8, 1=int32, 2=float32

// ---------------------------------------------------------------------------
// Helpers
// ---------------------------------------------------------------------------
__device__ __forceinline__ uint32_t smem_to_u32(const void* p) {
    uint32_t a;
    asm("{ .reg .u64 t; cvta.to.shared.u64 t, %1; cvt.u32.u64 %0, t; }" : "=r"(a) : "l"(p));
    return a;
}

__device__ __forceinline__ void cp_async16(uint32_t dst, const void* src, int src_size) {
    asm volatile("cp.async.cg.shared.global [%0], [%1], 16, %2;"
                 :: "r"(dst), "l"(src), "r"(src_size) : "memory");
}
__device__ __forceinline__ void cp_commit() {
    asm volatile("cp.async.commit_group;" ::: "memory");
}
__device__ __forceinline__ void cp_wait1() {
    asm volatile("cp.async.wait_group 1;" ::: "memory");
}

// ---------------------------------------------------------------------------
// Mask dtype sniffing
// ---------------------------------------------------------------------------
__global__ void detect_mask_kernel(const unsigned int* __restrict__ pos) {
    __shared__ int any_big;
    __shared__ int any_f32;
    if (threadIdx.x == 0) { any_big = 0; any_f32 = 0; }
    __syncthreads();
    for (int i = threadIdx.x; i < 4096; i += 256) {
        unsigned int v = pos[i];
        if (v == 0x3F800000u) any_f32 = 1;
        else if (v > 1u)      any_big = 1;
    }
    __syncthreads();
    if (threadIdx.x == 0) d_mask_kind = any_f32 ? 2 : (any_big ? 0 : 1);
}

// ---------------------------------------------------------------------------
// Weights: masks (K,O) -> fp16 [o][k'] with k' = tap*256 + c   (k = c*9 + tap)
// ---------------------------------------------------------------------------
__global__ void prep_w_kernel(const void* __restrict__ posv,
                              const void* __restrict__ negv) {
    int i = blockIdx.x * 256 + threadIdx.x;   // over K*O
    if (i >= KK_ * O_) return;
    int k = i / O_;
    int o = i - k * O_;
    float p, n;
    int kind = d_mask_kind;
    if (kind == 1)      { p = (float)((const int*)posv)[i];   n = (float)((const int*)negv)[i]; }
    else if (kind == 2) { p = ((const float*)posv)[i];        n = ((const float*)negv)[i]; }
    else                { p = (float)((const unsigned char*)posv)[i];
                          n = (float)((const unsigned char*)negv)[i]; }
    int c = k / 9;
    int t = k - c * 9;
    d_Wh[o * KK_ + t * 256 + c] = __float2half(p - n);
}

// ---------------------------------------------------------------------------
// x (b,c,hw) fp32 -> x^T (b,hw,c) fp16, tiled SMEM transpose.
// Tile: 128 channels x 32 pixels. Loads: float/lane (128B/warp), 16 rows/thread.
// Stores: uint2 = 4 halfs/lane (256B/warp), 4 hw-rows/thread.
// grid (HW/32, C/128, B), block (32, 8)
// ---------------------------------------------------------------------------
__global__ void prep_xt_kernel(const float* __restrict__ x) {
    __shared__ __half tile[128][33];   // [c][hw], padded
    int hw0 = blockIdx.x * 32;
    int c0  = blockIdx.y * 128;
    int b   = blockIdx.z;
    int tx = threadIdx.x, ty = threadIdx.y;
    const float* xp = x + (size_t)b * C_ * HW_;
    // load 128 c-rows x 32 hw: each thread 16 rows
#pragma unroll
    for (int r = 0; r < 16; ++r)
        tile[ty + 8 * r][tx] = __float2half(xp[(size_t)(c0 + ty + 8 * r) * HW_ + hw0 + tx]);
    __syncthreads();
    // store 32 hw-rows x 128 c as 32 uint2 per row: each thread 4 rows, 1 uint2/row
    uint2* xt4 = reinterpret_cast<uint2*>(d_xt_buf + XPAD + (size_t)b * HW_ * C_);
#pragma unroll
    for (int r = 0; r < 4; ++r) {              // 32 hw rows / 8 ty lanes
        int hwrow = ty + 8 * r;                // 0..31
        __half2 va = __halves2half2(tile[4 * tx][hwrow],     tile[4 * tx + 1][hwrow]);
        __half2 vb = __halves2half2(tile[4 * tx + 2][hwrow], tile[4 * tx + 3][hwrow]);
        uint2 v;
        v.x = *reinterpret_cast<unsigned int*>(&va);
        v.y = *reinterpret_cast<unsigned int*>(&vb);
        xt4[(size_t)(hw0 + hwrow) * (C_ / 4) + c0 / 4 + tx] = v;
    }
}

// ---------------------------------------------------------------------------
// Implicit-GEMM conv, wmma + 3-stage cp.async pipeline (BK=64), 2 CTAs/SM.
// CTA: BM=128 o-channels x BN=128 pixels. 8 warps, warp grid 4(M) x 2(N),
// warp tile 32x64 -> acc[2][4] wmma 16x16x16 fragments (f16 in, f32 acc).
// K chunks: 36 x 64 (one tap x 64 contiguous channels in x^T layout).
// Epilogue: DIRECT store_matrix_sync to global (fragments are 16-pixel
// aligned and 3136 % 16 == 0, so no fragment straddles a batch boundary).
// ---------------------------------------------------------------------------
__global__ __launch_bounds__(NTHREADS, 2)
void conv_gemm_kernel(float* __restrict__ out) {
    extern __shared__ __align__(1024) char smem[];
    const uint32_t smem_base = smem_to_u32(smem);
    const int tid = threadIdx.x;

    int* sXoff = (int*)(smem + SM_META);          // (b*HW + hw) * C
    int* sHW   = (int*)(smem + SM_META + 512);    // h<<16 | w

    const int n0 = blockIdx.x * BN;    // pixel tile
    const int m0 = blockIdx.y * BM;    // output-channel tile

    if (tid < BN) {
        int n  = n0 + tid;
        int b  = n / HW_;
        int hw = n - b * HW_;
        int h  = hw / W_;
        int w  = hw - h * W_;
        sXoff[tid] = (b * HW_ + hw) * C_;
        sHW[tid]   = (h << 16) | w;
    }
    __syncthreads();

    // ---- hoisted loader state ----
    // task idx = tid + 256*r: seg = tid&7 (constant), m/j = (tid>>3)+32r
    const int sg      = tid & 7;
    const int mj_base = tid >> 3;

    const __half*  aSrcBase = d_Wh + (size_t)(m0 + mj_base) * KK_ + sg * 8;
    const uint32_t aOffBase = smem_base + mj_base * ROW_B + sg * 16;

    const __half* bSrc[4];
    uint32_t      bOff[4];
    uint32_t      vmask[4];   // bit t set => tap t in-bounds for this pixel
#pragma unroll
    for (int r = 0; r < 4; ++r) {
        int j   = mj_base + 32 * r;
        int hwp = sHW[j];
        int h = hwp >> 16, w = hwp & 0xFFFF;
        uint32_t msk = 0;
#pragma unroll
        for (int t = 0; t < 9; ++t) {
            int dh = t / 3 - 1;
            int dw = t - (t / 3) * 3 - 1;
            if ((unsigned)(h + dh) < (unsigned)H_ && (unsigned)(w + dw) < (unsigned)W_)
                msk |= 1u << t;
        }
        vmask[r] = msk;
        bSrc[r]  = d_xt_buf + XPAD + sXoff[j] + sg * 8;
        bOff[r]  = smem_base + A_BYTES + j * ROW_B + sg * 16;
    }

    // ---- stage loader: chunk i -> stage i % NSTAGES ----
    auto issue_loads = [&](int i) {
        const int s    = i % NSTAGES;
        const int t    = i >> 2;                  // tap 0..8 (4 chunks per tap)
        const int dh   = t / 3 - 1;
        const int dw   = t - (t / 3) * 3 - 1;
        const int koff = i * BK;                  // == t*256 + (i&3)*64
        const int boff = (dh * W_ + dw) * C_ + (i & 3) * BK;
        const uint32_t sb = (uint32_t)(s * STAGE_B);
#pragma unroll
        for (int r = 0; r < 4; ++r)
            cp_async16(aOffBase + sb + r * (32 * ROW_B),
                       aSrcBase + koff + (size_t)r * (32 * KK_), 16);
#pragma unroll
        for (int r = 0; r < 4; ++r)
            cp_async16(bOff[r] + sb, bSrc[r] + boff,
                       ((vmask[r] >> t) & 1u) ? 16 : 0);
    };

    const int wid = tid >> 5;
    const int wm  = wid >> 1;   // 0..3 (M)
    const int wn  = wid & 1;    // 0..1 (N)

    wmma::fragment<wmma::accumulator, 16, 16, 16, float> acc[2][4];
#pragma unroll
    for (int im = 0; im < 2; ++im)
#pragma unroll
        for (int in = 0; in < 4; ++in)
            wmma::fill_fragment(acc[im][in], 0.0f);

    // ---- prologue: 2 stages in flight ----
#pragma unroll
    for (int i = 0; i < NSTAGES - 1; ++i) { issue_loads(i); cp_commit(); }

    // ---- main loop ----
    for (int i = 0; i < NCHUNK; ++i) {
        cp_wait1();
        __syncthreads();

        const int s = i % NSTAGES;
        const __half* as = (const __half*)(smem + s * STAGE_B);
        const __half* bs = (const __half*)(smem + s * STAGE_B + A_BYTES);
#pragma unroll
        for (int kk = 0; kk < BK; kk += 16) {
            wmma::fragment<wmma::matrix_a, 16, 16, 16, __half, wmma::row_major> af[2];
            wmma::fragment<wmma::matrix_b, 16, 16, 16, __half, wmma::col_major> bf[4];
#pragma unroll
            for (int im = 0; im < 2; ++im)
                wmma::load_matrix_sync(af[im], as + (wm * 32 + im * 16) * 72 + kk, 72);
#pragma unroll
            for (int in = 0; in < 4; ++in)
                wmma::load_matrix_sync(bf[in], bs + (wn * 64 + in * 16) * 72 + kk, 72);
#pragma unroll
            for (int im = 0; im < 2; ++im)
#pragma unroll
                for (int in = 0; in < 4; ++in)
                    wmma::mma_sync(acc[im][in], af[im], bf[in], acc[im][in]);
        }

        if (i + NSTAGES - 1 < NCHUNK) issue_loads(i + NSTAGES - 1);
        cp_commit();   // unconditional: keeps wait_group accounting exact
    }

    // ---- epilogue: direct global stores, one fragment at a time ----
    // Fragment pixels [n0+p, n0+p+16) never straddle a batch (3136 % 16 == 0).
#pragma unroll
    for (int im = 0; im < 2; ++im)
#pragma unroll
        for (int in = 0; in < 4; ++in) {
            int p  = wn * 64 + in * 16;       // pixel offset in tile
            int n  = n0 + p;
            int b  = n / HW_;
            int hw = n - b * HW_;
            float* dst = out + (size_t)b * (O_ * HW_)
                             + (size_t)(m0 + wm * 32 + im * 16) * HW_ + hw;
            wmma::store_matrix_sync(dst, acc[im][in], HW_, wmma::mem_row_major);
        }
}

// ---------------------------------------------------------------------------
// Launch
// ---------------------------------------------------------------------------
extern "C" void kernel_launch(void* const* d_in, const int* in_sizes, int n_in,
                              void* d_out, int out_size) {
    const float* x   = (const float*)d_in[0];
    const void*  pos = d_in[1];
    const void*  neg = d_in[2];
    float* out = (float*)d_out;

    static bool attr_set = false;
    if (!attr_set) {
        cudaFuncSetAttribute(conv_gemm_kernel,
                             cudaFuncAttributeMaxDynamicSharedMemorySize, SMEM_TOTAL);
        attr_set = true;
    }

    // 0) sniff mask representation
    detect_mask_kernel<<<1, 256>>>((const unsigned int*)pos);
    // 1) weights -> fp16 [o][k'] (tap-major K permutation)
    prep_w_kernel<<<(KK_ * O_ + 255) / 256, 256>>>(pos, neg);
    // 2) x -> fp16 transposed [b][hw][c], uint2 stores
    dim3 tgrid(HW_ / 32, C_ / 128, B_);
    prep_xt_kernel<<<tgrid, dim3(32, 8)>>>(x);
    // 3) wmma implicit GEMM: grid = (784 pixel tiles, 4 m tiles), 2 CTAs/SM
    dim3 grid(NPIX / BN, O_ / BM);
    conv_gemm_kernel<<<grid, NTHREADS, SMEM_TOTAL>>>(out);
}